// round 1
// baseline (speedup 1.0000x reference)
#include <cuda_runtime.h>
#include <math.h>

#define B_   128
#define PP_  1024
#define LP_  128
#define H_   256
#define NP_  (B_*PP_)
#define NL_  (B_*LP_)

// ---- device scratch (no allocations allowed) ----
__device__ float g_Pelem[128 * H_];   // E_elem @ Wd1
__device__ float g_Paa  [32  * H_];   // E_aa   @ Wd1
__device__ float g_Pbb  [2   * H_];   // E_bb   @ Wd1 + bd1  (bias folded)
__device__ float g_Plig [16  * H_];   // E_lig  @ Wd1 + bd1  (bias folded)
__device__ float g_pool [2 * B_ * H_];   // per-batch SUMS of silu(pre): [0..127]=protein, [128..255]=ligand
__device__ float g_poolh[2 * B_ * H_];   // pooled means @ Wd2 + bd2
__device__ float g_contact[B_ * 2];

__device__ __forceinline__ float fast_silu(float x) {
    // silu(x) = 0.5*x*(1 + tanh(0.5*x)); tanh.approx is 1 MUFU op.
    float h = 0.5f * x;
    float t;
    asm("tanh.approx.f32 %0, %1;" : "=f"(t) : "f"(h));
    return h + h * t;
}

// ---- K0: zero the pooling accumulators (must happen every launch) ----
__global__ void k_zero() {
    g_pool[blockIdx.x * blockDim.x + threadIdx.x] = 0.f;
}

// ---- K1: project the 4 embedding tables through Wd1 (178 rows x 256 x 256) ----
__global__ __launch_bounds__(256) void k_project(
    const float* __restrict__ E_elem, const float* __restrict__ E_aa,
    const float* __restrict__ E_bb,   const float* __restrict__ E_lig,
    const float* __restrict__ Wd1,    const float* __restrict__ bd1) {
    __shared__ float s[H_];
    int r = blockIdx.x, j = threadIdx.x;
    const float* src; float* dst; bool bias;
    if      (r < 128) { src = E_elem + r * H_;        dst = g_Pelem + r * H_;        bias = false; }
    else if (r < 160) { src = E_aa  + (r - 128) * H_; dst = g_Paa  + (r - 128) * H_; bias = false; }
    else if (r < 162) { src = E_bb  + (r - 160) * H_; dst = g_Pbb  + (r - 160) * H_; bias = true;  }
    else              { src = E_lig + (r - 162) * H_; dst = g_Plig + (r - 162) * H_; bias = true;  }
    s[j] = src[j];
    __syncthreads();
    float acc = bias ? bd1[j] : 0.f;
    #pragma unroll 8
    for (int k = 0; k < H_; k++) acc += s[k] * Wd1[k * H_ + j];
    dst[j] = acc;
}

// ---- K2: fused gather + add + silu + per-batch column sums ----
__device__ __forceinline__ void acc_silu3(float4& acc, float4 a, float4 b, float4 c) {
    acc.x += fast_silu(a.x + b.x + c.x);
    acc.y += fast_silu(a.y + b.y + c.y);
    acc.z += fast_silu(a.z + b.z + c.z);
    acc.w += fast_silu(a.w + b.w + c.w);
}
__device__ __forceinline__ void acc_silu1(float4& acc, float4 a) {
    acc.x += fast_silu(a.x);
    acc.y += fast_silu(a.y);
    acc.z += fast_silu(a.z);
    acc.w += fast_silu(a.w);
}

__global__ __launch_bounds__(256) void k_fuse(
    const int* __restrict__ pelem, const int* __restrict__ paa,
    const int* __restrict__ pbb,   const int* __restrict__ pbatch,
    const int* __restrict__ ltype, const int* __restrict__ lbatch) {
    __shared__ float s_red[8 * H_];     // 8 KB cross-warp reduction
    __shared__ float s_tab[16 * H_];    // 16 KB: P_lig (ligand) or P_bb (protein, first 2KB)
    __shared__ int   s_i0[128], s_i1[128], s_i2[128];
    int tid = threadIdx.x, warp = tid >> 5, lane = tid & 31;
    float4 acc0 = make_float4(0, 0, 0, 0), acc1 = make_float4(0, 0, 0, 0);
    float* pool;

    if (blockIdx.x < 1024) {            // protein: 128 rows per CTA, all same batch
        int row0 = blockIdx.x * 128;
        if (tid < 128) {
            s_i0[tid] = pelem[row0 + tid];
            s_i1[tid] = paa[row0 + tid];
            s_i2[tid] = pbb[row0 + tid];
        }
        for (int i = tid; i < 2 * H_; i += 256) s_tab[i] = g_Pbb[i];
        int batch = pbatch[row0];
        pool = g_pool + batch * H_;
        __syncthreads();
        const float4* Pe = reinterpret_cast<const float4*>(g_Pelem);
        const float4* Pa = reinterpret_cast<const float4*>(g_Paa);
        const float4* Pb = reinterpret_cast<const float4*>(s_tab);
        #pragma unroll 4
        for (int i = 0; i < 16; i++) {
            int r = warp * 16 + i;
            int e = s_i0[r] << 6, a = s_i1[r] << 6, bb = s_i2[r] << 6;
            float4 x0 = Pe[e + lane],      y0 = Pa[a + lane],      z0 = Pb[bb + lane];
            float4 x1 = Pe[e + 32 + lane], y1 = Pa[a + 32 + lane], z1 = Pb[bb + 32 + lane];
            acc_silu3(acc0, x0, y0, z0);
            acc_silu3(acc1, x1, y1, z1);
        }
    } else {                            // ligand: 128 rows per CTA = one batch
        int row0 = (blockIdx.x - 1024) * 128;
        if (tid < 128) s_i0[tid] = ltype[row0 + tid];
        for (int i = tid; i < 16 * H_; i += 256) s_tab[i] = g_Plig[i];
        int batch = lbatch[row0];
        pool = g_pool + (B_ + batch) * H_;
        __syncthreads();
        const float4* Pl = reinterpret_cast<const float4*>(s_tab);
        #pragma unroll 4
        for (int i = 0; i < 16; i++) {
            int r = warp * 16 + i;
            int t = s_i0[r] << 6;
            acc_silu1(acc0, Pl[t + lane]);
            acc_silu1(acc1, Pl[t + 32 + lane]);
        }
    }
    // lane l holds cols [4l,4l+4) in acc0 and [128+4l,128+4l+4) in acc1
    float* my = s_red + warp * H_;
    reinterpret_cast<float4*>(my)[lane]       = acc0;
    reinterpret_cast<float4*>(my + 128)[lane] = acc1;
    __syncthreads();
    float sum = 0.f;
    #pragma unroll
    for (int w = 0; w < 8; w++) sum += s_red[w * H_ + tid];
    atomicAdd(&pool[tid], sum);
}

// ---- K3: per-batch pairwise min distances -> contact features ----
__global__ __launch_bounds__(256) void k_dist(
    const float* __restrict__ ppos, const float* __restrict__ lpos) {
    __shared__ float4 s_p[PP_];     // 16 KB
    __shared__ float  s_half[256];
    __shared__ float  s_d[128];
    int b = blockIdx.x, tid = threadIdx.x;
    const float* pp = ppos + (size_t)b * PP_ * 3;
    for (int i = tid; i < PP_; i += 256)
        s_p[i] = make_float4(pp[3 * i], pp[3 * i + 1], pp[3 * i + 2], 0.f);
    __syncthreads();
    int lig = tid & (LP_ - 1), half = tid >> 7;
    const float* lp = lpos + ((size_t)b * LP_ + lig) * 3;
    float lx = lp[0], ly = lp[1], lz = lp[2];
    float m0 = 3.4e38f, m1 = 3.4e38f, m2 = 3.4e38f, m3 = 3.4e38f;
    int p0 = half * 512;
    for (int p = p0; p < p0 + 512; p += 4) {
        float4 q;
        q = s_p[p];     { float dx = lx - q.x, dy = ly - q.y, dz = lz - q.z; m0 = fminf(m0, dx * dx + dy * dy + dz * dz); }
        q = s_p[p + 1]; { float dx = lx - q.x, dy = ly - q.y, dz = lz - q.z; m1 = fminf(m1, dx * dx + dy * dy + dz * dz); }
        q = s_p[p + 2]; { float dx = lx - q.x, dy = ly - q.y, dz = lz - q.z; m2 = fminf(m2, dx * dx + dy * dy + dz * dz); }
        q = s_p[p + 3]; { float dx = lx - q.x, dy = ly - q.y, dz = lz - q.z; m3 = fminf(m3, dx * dx + dy * dy + dz * dz); }
    }
    s_half[tid] = fminf(fminf(m0, m1), fminf(m2, m3));
    __syncthreads();
    if (tid < 128) s_d[tid] = sqrtf(fminf(s_half[tid], s_half[tid + 128]));
    __syncthreads();
    if (tid < 32) {
        float sum = 0.f, mn = 3.4e38f;
        #pragma unroll
        for (int i = 0; i < 4; i++) { float v = s_d[tid + 32 * i]; sum += v; mn = fminf(mn, v); }
        #pragma unroll
        for (int o = 16; o > 0; o >>= 1) {
            sum += __shfl_xor_sync(0xffffffffu, sum, o);
            mn = fminf(mn, __shfl_xor_sync(0xffffffffu, mn, o));
        }
        if (tid == 0) { g_contact[2 * b] = sum * (1.f / LP_); g_contact[2 * b + 1] = mn; }
    }
}

// ---- K4: pooled means through Wd2 (256 rows x 256 x 256) ----
__global__ __launch_bounds__(256) void k_poolh(
    const float* __restrict__ Wd2, const float* __restrict__ bd2) {
    __shared__ float s[H_];
    int r = blockIdx.x, j = threadIdx.x;
    float inv = (r < B_) ? (1.f / PP_) : (1.f / LP_);
    s[j] = g_pool[r * H_ + j] * inv;
    __syncthreads();
    float acc = bd2[j];
    #pragma unroll 8
    for (int k = 0; k < H_; k++) acc += s[k] * Wd2[k * H_ + j];
    g_poolh[r * H_ + j] = acc;
}

// ---- K5: final affinity MLP (128 rows x 514 -> 256 -> 1), exact silu ----
__global__ __launch_bounds__(256) void k_aff(
    const float* __restrict__ Wa1, const float* __restrict__ ba1,
    const float* __restrict__ Wa2, const float* __restrict__ ba2,
    float* __restrict__ out) {
    __shared__ float gf[2 * H_ + 2];
    __shared__ float s_red[256];
    int b = blockIdx.x, j = threadIdx.x;
    gf[j]       = g_poolh[b * H_ + j];
    gf[H_ + j]  = g_poolh[(B_ + b) * H_ + j];
    if (j < 2) gf[2 * H_ + j] = g_contact[2 * b + j];
    __syncthreads();
    float a = ba1[j];
    #pragma unroll 2
    for (int k = 0; k < 2 * H_ + 2; k++) a += gf[k] * Wa1[k * H_ + j];
    float h = a / (1.f + expf(-a));      // accurate silu here (direct path to output)
    s_red[j] = h * Wa2[j];
    __syncthreads();
    for (int s = 128; s > 0; s >>= 1) {
        if (j < s) s_red[j] += s_red[j + s];
        __syncthreads();
    }
    if (j == 0) out[b] = s_red[0] + ba2[0];
}

extern "C" void kernel_launch(void* const* d_in, const int* in_sizes, int n_in,
                              void* d_out, int out_size) {
    const float* protein_pos     = (const float*)d_in[0];
    const float* ligand_pos      = (const float*)d_in[1];
    const int*   protein_element = (const int*)  d_in[2];
    const int*   protein_aa      = (const int*)  d_in[3];
    const int*   protein_bb      = (const int*)  d_in[4];
    const int*   ligand_type     = (const int*)  d_in[5];
    const int*   protein_batch   = (const int*)  d_in[6];
    const int*   ligand_batch    = (const int*)  d_in[7];
    const float* E_elem          = (const float*)d_in[8];
    const float* E_aa            = (const float*)d_in[9];
    const float* E_bb            = (const float*)d_in[10];
    const float* E_lig           = (const float*)d_in[11];
    const float* Wd1             = (const float*)d_in[12];
    const float* bd1             = (const float*)d_in[13];
    const float* Wd2             = (const float*)d_in[14];
    const float* bd2             = (const float*)d_in[15];
    const float* Wa1             = (const float*)d_in[16];
    const float* ba1             = (const float*)d_in[17];
    const float* Wa2             = (const float*)d_in[18];
    const float* ba2             = (const float*)d_in[19];
    float* out = (float*)d_out;

    k_zero   <<<256, 256>>>();                       // 65536 accumulators
    k_project<<<178, 256>>>(E_elem, E_aa, E_bb, E_lig, Wd1, bd1);
    k_dist   <<<B_,  256>>>(protein_pos, ligand_pos);
    k_fuse   <<<1152, 256>>>(protein_element, protein_aa, protein_bb,
                             protein_batch, ligand_type, ligand_batch);
    k_poolh  <<<256, 256>>>(Wd2, bd2);
    k_aff    <<<B_,  256>>>(Wa1, ba1, Wa2, ba2, out);
}

// round 2
// speedup vs baseline: 1.3670x; 1.3670x over previous
#include <cuda_runtime.h>
#include <math.h>

#define B_   128
#define PP_  1024
#define LP_  128
#define H_   256

typedef unsigned long long u64;

// ---- device scratch ----
__device__ float g_Pelem[128 * H_];    // E_elem @ Wd1
__device__ float g_Paa  [32  * H_];    // E_aa   @ Wd1
__device__ float g_Pbb  [2   * H_];    // E_bb   @ Wd1 + bd1
__device__ float g_sPlig[16  * H_];    // silu(E_lig @ Wd1 + bd1)
__device__ float g_M    [512 * H_];    // [Wd2@Wa1_p ; Wd2@Wa1_l]
__device__ float g_bvec [H_];          // ba1 + bd2@(Wa1_p+Wa1_l)
__device__ float g_pool [2 * B_ * H_]; // per-batch SUMS of silu
__device__ float g_contact[B_ * 2];

// ---- packed f32x2 helpers (Blackwell) ----
__device__ __forceinline__ u64 f2_add(u64 a, u64 b){u64 r;asm("add.rn.f32x2 %0,%1,%2;":"=l"(r):"l"(a),"l"(b));return r;}
__device__ __forceinline__ u64 f2_mul(u64 a, u64 b){u64 r;asm("mul.rn.f32x2 %0,%1,%2;":"=l"(r):"l"(a),"l"(b));return r;}
__device__ __forceinline__ u64 f2_fma(u64 a, u64 b, u64 c){u64 r;asm("fma.rn.f32x2 %0,%1,%2,%3;":"=l"(r):"l"(a),"l"(b),"l"(c));return r;}
__device__ __forceinline__ u64 f2_pack(float x, float y){
    unsigned xi = __float_as_uint(x), yi = __float_as_uint(y);
    u64 r; asm("mov.b64 %0,{%1,%2};":"=l"(r):"r"(xi),"r"(yi)); return r;
}
__device__ __forceinline__ float2 f2_unpack(u64 a){
    unsigned lo, hi; asm("mov.b64 {%0,%1},%2;":"=r"(lo),"=r"(hi):"l"(a));
    return make_float2(__uint_as_float(lo), __uint_as_float(hi));
}

// silu-poly accumulate: acc += s*(0.5 + 0.25 s - s^3/48), s = a+b+c  (valid |s| << 1)
__device__ __forceinline__ u64 silu_acc(u64 acc, u64 a, u64 b, u64 c, u64 C0, u64 C1, u64 C2){
    u64 s  = f2_add(f2_add(a, b), c);
    u64 x2 = f2_mul(s, s);
    u64 w  = f2_fma(x2, C2, C1);
    u64 u  = f2_fma(s, w, C0);
    return f2_fma(s, u, acc);
}

// ================= Stage 1: projections + M precompute + misc init =================
// blocks [0,45)   : project 4 rows of the 178 stacked embedding rows through Wd1
// blocks [45,173) : M = Wd2 @ Wa1 slices, 4 out-rows per block (512 rows total)
// blocks [173,181): zero protein half of g_pool
// block  181      : bvec
// block  182      : out[b] = ba2
__global__ __launch_bounds__(256) void k_stage1(
    const float* __restrict__ Ee, const float* __restrict__ Ea,
    const float* __restrict__ Eb, const float* __restrict__ El,
    const float* __restrict__ Wd1, const float* __restrict__ bd1,
    const float* __restrict__ Wd2, const float* __restrict__ Wa1,
    const float* __restrict__ ba1, const float* __restrict__ bd2,
    const float* __restrict__ ba2, float* __restrict__ out)
{
    int bid = blockIdx.x, tid = threadIdx.x;
    if (bid < 173) {
        __shared__ float s_at[H_ * 4];     // A rows, transposed: s_at[k*4 + r]
        const float* src[4]; float* dst[4]; int bias[4], dosilu[4], valid[4];
        const float* Bp;
        if (bid < 45) {
            Bp = Wd1;
            int r0 = bid * 4;
            #pragma unroll
            for (int r = 0; r < 4; r++) {
                int g = r0 + r; valid[r] = (g < 178); bias[r] = 0; dosilu[r] = 0;
                int gc = valid[r] ? g : 0;
                if      (gc < 128) { src[r] = Ee + gc * H_;        dst[r] = g_Pelem + gc * H_; }
                else if (gc < 160) { src[r] = Ea + (gc-128) * H_;  dst[r] = g_Paa  + (gc-128) * H_; }
                else if (gc < 162) { src[r] = Eb + (gc-160) * H_;  dst[r] = g_Pbb  + (gc-160) * H_; bias[r] = 1; }
                else               { src[r] = El + (gc-162) * H_;  dst[r] = g_sPlig+ (gc-162) * H_; bias[r] = 1; dosilu[r] = 1; }
            }
        } else {
            int R = (bid - 45) * 4;                    // 0..508
            Bp = (R < 256) ? Wa1 : (Wa1 + 256 * H_);
            #pragma unroll
            for (int r = 0; r < 4; r++) {
                src[r] = Wd2 + ((R + r) & 255) * H_;
                dst[r] = g_M + (R + r) * H_;
                bias[r] = 0; dosilu[r] = 0; valid[r] = 1;
            }
        }
        for (int idx = tid; idx < 4 * H_; idx += 256) {
            int k = idx >> 2, r = idx & 3;
            s_at[idx] = src[r][k];
        }
        __syncthreads();
        float a0 = 0, a1 = 0, a2 = 0, a3 = 0;
        const float4* sa4 = (const float4*)s_at;
        int j = tid;
        #pragma unroll 8
        for (int k = 0; k < H_; k++) {
            float w = Bp[k * H_ + j];
            float4 av = sa4[k];
            a0 += av.x * w; a1 += av.y * w; a2 += av.z * w; a3 += av.w * w;
        }
        float acc[4] = {a0, a1, a2, a3};
        float bj = bd1[j];
        #pragma unroll
        for (int r = 0; r < 4; r++) {
            if (!valid[r]) continue;
            float v = acc[r] + (bias[r] ? bj : 0.f);
            if (dosilu[r]) v = v / (1.f + expf(-v));
            dst[r][j] = v;
        }
    } else if (bid < 181) {
        int base = (bid - 173) * 4096;
        for (int i = tid; i < 4096; i += 256) g_pool[base + i] = 0.f;
    } else if (bid == 181) {
        __shared__ float sb[256];
        sb[tid] = bd2[tid];
        __syncthreads();
        float v = ba1[tid];
        #pragma unroll 8
        for (int k = 0; k < 512; k++) v += sb[k & 255] * Wa1[k * H_ + tid];
        g_bvec[tid] = v;
    } else {
        if (tid < 128) out[tid] = ba2[0];
    }
}

// ================= K2: fused gather + poly-silu + per-batch sums =================
__global__ __launch_bounds__(256) void k_fuse(
    const int* __restrict__ pelem, const int* __restrict__ paa,
    const int* __restrict__ pbb,   const int* __restrict__ pbatch,
    const int* __restrict__ ltype, const int* __restrict__ lbatch)
{
    int tid = threadIdx.x;
    if (blockIdx.x < 1024) {               // protein: 128 rows per CTA
        __shared__ float s_red[8 * H_];
        __shared__ int s_i0[128], s_i1[128], s_i2[128];
        int warp = tid >> 5, lane = tid & 31;
        int row0 = blockIdx.x * 128;
        if (tid < 128) {
            s_i0[tid] = pelem[row0 + tid];
            s_i1[tid] = paa[row0 + tid];
            s_i2[tid] = pbb[row0 + tid];
        }
        int batch = pbatch[row0];
        __syncthreads();
        u64 C0 = f2_pack(0.5f, 0.5f), C1 = f2_pack(0.25f, 0.25f),
            C2 = f2_pack(-1.f/48.f, -1.f/48.f);
        u64 acc00 = 0, acc01 = 0, acc10 = 0, acc11 = 0;
        const ulonglong2* Pe = (const ulonglong2*)g_Pelem;
        const ulonglong2* Pa = (const ulonglong2*)g_Paa;
        const ulonglong2* Pb = (const ulonglong2*)g_Pbb;
        #pragma unroll 4
        for (int i = 0; i < 16; i++) {
            int r = warp * 16 + i;
            int e = s_i0[r] << 6, a = s_i1[r] << 6, bb = s_i2[r] << 6;
            ulonglong2 A0 = Pe[e + lane],      Bv0 = Pa[a + lane],      Cv0 = Pb[bb + lane];
            ulonglong2 A1 = Pe[e + 32 + lane], Bv1 = Pa[a + 32 + lane], Cv1 = Pb[bb + 32 + lane];
            acc00 = silu_acc(acc00, A0.x, Bv0.x, Cv0.x, C0, C1, C2);
            acc01 = silu_acc(acc01, A0.y, Bv0.y, Cv0.y, C0, C1, C2);
            acc10 = silu_acc(acc10, A1.x, Bv1.x, Cv1.x, C0, C1, C2);
            acc11 = silu_acc(acc11, A1.y, Bv1.y, Cv1.y, C0, C1, C2);
        }
        float* my = s_red + warp * H_;
        ((ulonglong2*)my)[lane]         = make_ulonglong2(acc00, acc01);
        ((ulonglong2*)(my + 128))[lane] = make_ulonglong2(acc10, acc11);
        __syncthreads();
        float sum = 0.f;
        #pragma unroll
        for (int w = 0; w < 8; w++) sum += s_red[w * H_ + tid];
        atomicAdd(&g_pool[batch * H_ + tid], sum);
    } else {                               // ligand: histogram over 16 types
        __shared__ int s_cnt[16];
        int bl = blockIdx.x - 1024;
        if (tid < 16) s_cnt[tid] = 0;
        __syncthreads();
        if (tid < 128) atomicAdd(&s_cnt[ltype[bl * 128 + tid]], 1);
        int batch = lbatch[bl * 128];
        __syncthreads();
        float sum = 0.f;
        #pragma unroll
        for (int t = 0; t < 16; t++) sum += (float)s_cnt[t] * g_sPlig[t * H_ + tid];
        g_pool[(B_ + batch) * H_ + tid] = sum;   // sole writer, no atomic/zero
    }
}

// ================= K3: pairwise min distances -> contact =================
__global__ __launch_bounds__(512) void k_dist(
    const float* __restrict__ ppos, const float* __restrict__ lpos)
{
    __shared__ float s_x[PP_], s_y[PP_], s_z[PP_];   // 12 KB SoA
    __shared__ float s_half[512];
    __shared__ float s_d[128];
    int b = blockIdx.x, tid = threadIdx.x;
    const float* pp = ppos + (size_t)b * PP_ * 3;
    for (int i = tid; i < PP_; i += 512) {
        s_x[i] = pp[3 * i]; s_y[i] = pp[3 * i + 1]; s_z[i] = pp[3 * i + 2];
    }
    __syncthreads();
    int lig = tid & (LP_ - 1), q = tid >> 7;          // quarter 0..3, 256 pts each
    const float* lp = lpos + ((size_t)b * LP_ + lig) * 3;
    float lx = lp[0], ly = lp[1], lz = lp[2];
    u64 NX = f2_pack(-lx, -lx), NY = f2_pack(-ly, -ly), NZ = f2_pack(-lz, -lz);
    const ulonglong2* sx = (const ulonglong2*)s_x + q * 64;
    const ulonglong2* sy = (const ulonglong2*)s_y + q * 64;
    const ulonglong2* sz = (const ulonglong2*)s_z + q * 64;
    float m0 = 3.4e38f, m1 = 3.4e38f, m2 = 3.4e38f, m3 = 3.4e38f;
    #pragma unroll 4
    for (int i = 0; i < 64; i++) {
        ulonglong2 X = sx[i], Y = sy[i], Z = sz[i];
        u64 dx = f2_add(X.x, NX), dy = f2_add(Y.x, NY), dz = f2_add(Z.x, NZ);
        u64 d2 = f2_fma(dz, dz, f2_fma(dy, dy, f2_mul(dx, dx)));
        float2 u = f2_unpack(d2);
        m0 = fminf(m0, u.x); m1 = fminf(m1, u.y);
        dx = f2_add(X.y, NX); dy = f2_add(Y.y, NY); dz = f2_add(Z.y, NZ);
        d2 = f2_fma(dz, dz, f2_fma(dy, dy, f2_mul(dx, dx)));
        u = f2_unpack(d2);
        m2 = fminf(m2, u.x); m3 = fminf(m3, u.y);
    }
    s_half[tid] = fminf(fminf(m0, m1), fminf(m2, m3));
    __syncthreads();
    if (tid < 128) {
        float v = fminf(fminf(s_half[tid], s_half[tid + 128]),
                        fminf(s_half[tid + 256], s_half[tid + 384]));
        s_d[tid] = sqrtf(v);
    }
    __syncthreads();
    if (tid < 32) {
        float sum = 0.f, mn = 3.4e38f;
        #pragma unroll
        for (int i = 0; i < 4; i++) { float v = s_d[tid + 32 * i]; sum += v; mn = fminf(mn, v); }
        #pragma unroll
        for (int o = 16; o > 0; o >>= 1) {
            sum += __shfl_xor_sync(0xffffffffu, sum, o);
            mn = fminf(mn, __shfl_xor_sync(0xffffffffu, mn, o));
        }
        if (tid == 0) { g_contact[2 * b] = sum * (1.f / LP_); g_contact[2 * b + 1] = mn; }
    }
}

// ================= K4: final affinity (tiled over batches x col-halves) =================
// grid 32: bid = (bg<<1)|ct. 8 batches x 128 cols per CTA, second layer via atomicAdd.
__global__ __launch_bounds__(256) void k_aff(
    const float* __restrict__ Wa1, const float* __restrict__ Wa2,
    float* __restrict__ out)
{
    __shared__ float s_at[512 * 8];    // means, transposed: s_at[k*8 + bb]  (16 KB)
    __shared__ float s_p[8][128];
    int bid = blockIdx.x, tid = threadIdx.x;
    int ct = bid & 1, bg = bid >> 1;
    for (int idx = tid; idx < 4096; idx += 256) {
        int k = idx >> 3, bb = idx & 7, b = bg * 8 + bb;
        float v = (k < 256) ? g_pool[b * H_ + k] * (1.f / PP_)
                            : g_pool[(B_ + b) * H_ + (k - 256)] * (1.f / LP_);
        s_at[idx] = v;
    }
    __syncthreads();
    int j = tid & 127, p = tid >> 7, jj = ct * 128 + j;
    float a0 = 0, a1 = 0, a2 = 0, a3 = 0;
    const float4* sa = (const float4*)s_at;       // index k*2 + p -> 4 batches
    #pragma unroll 8
    for (int k = 0; k < 512; k++) {
        float w = g_M[k * H_ + jj];
        float4 av = sa[k * 2 + p];
        a0 += av.x * w; a1 += av.y * w; a2 += av.z * w; a3 += av.w * w;
    }
    float w512 = Wa1[512 * H_ + jj], w513 = Wa1[513 * H_ + jj];
    float bj = g_bvec[jj], w2 = Wa2[jj];
    float acc[4] = {a0, a1, a2, a3};
    #pragma unroll
    for (int r = 0; r < 4; r++) {
        int b = bg * 8 + p * 4 + r;
        float a = acc[r] + g_contact[2 * b] * w512 + g_contact[2 * b + 1] * w513 + bj;
        float h = a / (1.f + expf(-a));            // exact silu on the output path
        s_p[p * 4 + r][j] = h * w2;
    }
    __syncthreads();
    int warp = tid >> 5, lane = tid & 31;
    float v = s_p[warp][lane] + s_p[warp][lane + 32] + s_p[warp][lane + 64] + s_p[warp][lane + 96];
    #pragma unroll
    for (int o = 16; o > 0; o >>= 1) v += __shfl_xor_sync(0xffffffffu, v, o);
    if (lane == 0) atomicAdd(&out[bg * 8 + warp], v);
}

extern "C" void kernel_launch(void* const* d_in, const int* in_sizes, int n_in,
                              void* d_out, int out_size) {
    const float* protein_pos     = (const float*)d_in[0];
    const float* ligand_pos      = (const float*)d_in[1];
    const int*   protein_element = (const int*)  d_in[2];
    const int*   protein_aa      = (const int*)  d_in[3];
    const int*   protein_bb      = (const int*)  d_in[4];
    const int*   ligand_type     = (const int*)  d_in[5];
    const int*   protein_batch   = (const int*)  d_in[6];
    const int*   ligand_batch    = (const int*)  d_in[7];
    const float* E_elem          = (const float*)d_in[8];
    const float* E_aa            = (const float*)d_in[9];
    const float* E_bb            = (const float*)d_in[10];
    const float* E_lig           = (const float*)d_in[11];
    const float* Wd1             = (const float*)d_in[12];
    const float* bd1             = (const float*)d_in[13];
    const float* Wd2             = (const float*)d_in[14];
    const float* bd2             = (const float*)d_in[15];
    const float* Wa1             = (const float*)d_in[16];
    const float* ba1             = (const float*)d_in[17];
    const float* Wa2             = (const float*)d_in[18];
    const float* ba2             = (const float*)d_in[19];
    float* out = (float*)d_out;

    k_stage1<<<183, 256>>>(E_elem, E_aa, E_bb, E_lig, Wd1, bd1, Wd2,
                           Wa1, ba1, bd2, ba2, out);
    k_fuse  <<<1152, 256>>>(protein_element, protein_aa, protein_bb,
                            protein_batch, ligand_type, ligand_batch);
    k_dist  <<<B_, 512>>>(protein_pos, ligand_pos);
    k_aff   <<<32, 256>>>(Wa1, Wa2, out);
}

// round 4
// speedup vs baseline: 1.9895x; 1.4554x over previous
#include <cuda_runtime.h>
#include <math.h>

#define B_   128
#define PP_  1024
#define LP_  128
#define H_   256

typedef unsigned long long u64;

// ---- device scratch ----
__device__ float g_Pelem[128 * H_];    // E_elem @ Wd1
__device__ float g_Paa  [32  * H_];    // E_aa   @ Wd1
__device__ float g_Pbb  [2   * H_];    // E_bb   @ Wd1 + bd1
__device__ float g_sPlig[16  * H_];    // silu(E_lig @ Wd1 + bd1)
__device__ float g_M    [512 * H_];    // [Wd2@Wa1_p ; Wd2@Wa1_l]
__device__ float g_bvec [H_];          // ba1 + bd2@(Wa1_p+Wa1_l)
__device__ float g_pool [2 * B_ * H_]; // per-batch SUMS of silu
__device__ float g_act  [B_ * H_];     // pre-activation partials
__device__ float g_contact[B_ * 2];

// ---- packed f32x2 helpers (Blackwell) ----
__device__ __forceinline__ u64 f2_add(u64 a, u64 b){u64 r;asm("add.rn.f32x2 %0,%1,%2;":"=l"(r):"l"(a),"l"(b));return r;}
__device__ __forceinline__ u64 f2_mul(u64 a, u64 b){u64 r;asm("mul.rn.f32x2 %0,%1,%2;":"=l"(r):"l"(a),"l"(b));return r;}
__device__ __forceinline__ u64 f2_fma(u64 a, u64 b, u64 c){u64 r;asm("fma.rn.f32x2 %0,%1,%2,%3;":"=l"(r):"l"(a),"l"(b),"l"(c));return r;}
__device__ __forceinline__ u64 f2_pack(float x, float y){
    unsigned xi = __float_as_uint(x), yi = __float_as_uint(y);
    u64 r; asm("mov.b64 %0,{%1,%2};":"=l"(r):"r"(xi),"r"(yi)); return r;
}
__device__ __forceinline__ float2 f2_unpack(u64 a){
    unsigned lo, hi; asm("mov.b64 {%0,%1},%2;":"=r"(lo),"=r"(hi):"l"(a));
    return make_float2(__uint_as_float(lo), __uint_as_float(hi));
}

// silu-poly accumulate: acc += s*(0.5 + 0.25 s - s^3/48), s = a+b+c  (valid |s| << 1)
__device__ __forceinline__ u64 silu_acc(u64 acc, u64 a, u64 b, u64 c, u64 C0, u64 C1, u64 C2){
    u64 s  = f2_add(f2_add(a, b), c);
    u64 x2 = f2_mul(s, s);
    u64 w  = f2_fma(x2, C2, C1);
    u64 u  = f2_fma(s, w, C0);
    return f2_fma(s, u, acc);
}

// ================= Stage 1: projections + M precompute + misc init =================
// [0,45)    : project 178 embedding rows (x4) through Wd1
// [45,173)  : M = Wd2 @ Wa1 slices (x4 rows)
// [173,181) : zero protein half of g_pool
// [181,189) : zero g_act
// 189       : bvec
__global__ __launch_bounds__(256) void k_stage1(
    const float* __restrict__ Ee, const float* __restrict__ Ea,
    const float* __restrict__ Eb, const float* __restrict__ El,
    const float* __restrict__ Wd1, const float* __restrict__ bd1,
    const float* __restrict__ Wd2, const float* __restrict__ Wa1,
    const float* __restrict__ ba1, const float* __restrict__ bd2)
{
    int bid = blockIdx.x, tid = threadIdx.x;
    if (bid < 173) {
        __shared__ float s_at[H_ * 4];     // A rows, transposed: s_at[k*4 + r]
        const float* src[4]; float* dst[4]; int bias[4], dosilu[4], valid[4];
        const float* Bp;
        if (bid < 45) {
            Bp = Wd1;
            int r0 = bid * 4;
            #pragma unroll
            for (int r = 0; r < 4; r++) {
                int g = r0 + r; valid[r] = (g < 178); bias[r] = 0; dosilu[r] = 0;
                int gc = valid[r] ? g : 0;
                if      (gc < 128) { src[r] = Ee + gc * H_;        dst[r] = g_Pelem + gc * H_; }
                else if (gc < 160) { src[r] = Ea + (gc-128) * H_;  dst[r] = g_Paa  + (gc-128) * H_; }
                else if (gc < 162) { src[r] = Eb + (gc-160) * H_;  dst[r] = g_Pbb  + (gc-160) * H_; bias[r] = 1; }
                else               { src[r] = El + (gc-162) * H_;  dst[r] = g_sPlig+ (gc-162) * H_; bias[r] = 1; dosilu[r] = 1; }
            }
        } else {
            int R = (bid - 45) * 4;                    // 0..508
            Bp = (R < 256) ? Wa1 : (Wa1 + 256 * H_);
            #pragma unroll
            for (int r = 0; r < 4; r++) {
                src[r] = Wd2 + ((R + r) & 255) * H_;
                dst[r] = g_M + (R + r) * H_;
                bias[r] = 0; dosilu[r] = 0; valid[r] = 1;
            }
        }
        for (int idx = tid; idx < 4 * H_; idx += 256) {
            int k = idx >> 2, r = idx & 3;
            s_at[idx] = src[r][k];
        }
        __syncthreads();
        float a0 = 0, a1 = 0, a2 = 0, a3 = 0;
        const float4* sa4 = (const float4*)s_at;
        int j = tid;
        #pragma unroll 8
        for (int k = 0; k < H_; k++) {
            float w = Bp[k * H_ + j];
            float4 av = sa4[k];
            a0 += av.x * w; a1 += av.y * w; a2 += av.z * w; a3 += av.w * w;
        }
        float acc[4] = {a0, a1, a2, a3};
        float bj = bd1[j];
        #pragma unroll
        for (int r = 0; r < 4; r++) {
            if (!valid[r]) continue;
            float v = acc[r] + (bias[r] ? bj : 0.f);
            if (dosilu[r]) v = v / (1.f + expf(-v));
            dst[r][j] = v;
        }
    } else if (bid < 181) {
        int base = (bid - 173) * 4096;
        for (int i = tid; i < 4096; i += 256) g_pool[base + i] = 0.f;
    } else if (bid < 189) {
        int base = (bid - 181) * 4096;
        for (int i = tid; i < 4096; i += 256) g_act[base + i] = 0.f;
    } else {
        __shared__ float sb[256];
        sb[tid] = bd2[tid];
        __syncthreads();
        float v = ba1[tid];
        #pragma unroll 8
        for (int k = 0; k < 512; k++) v += sb[k & 255] * Wa1[k * H_ + tid];
        g_bvec[tid] = v;
    }
}

// ================= K2: fused gather-silu-pool + ligand histogram + distances =================
// [0,1024)     protein pooling
// [1024,1152)  ligand histogram pooling
// [1152,1280)  contact distances
__global__ __launch_bounds__(256) void k_fused(
    const int* __restrict__ pelem, const int* __restrict__ paa,
    const int* __restrict__ pbb,   const int* __restrict__ pbatch,
    const int* __restrict__ ltype, const int* __restrict__ lbatch,
    const float* __restrict__ ppos, const float* __restrict__ lpos)
{
    __shared__ __align__(16) char smbuf[14080];
    int tid = threadIdx.x;
    if (blockIdx.x < 1024) {               // ---- protein: 128 rows per CTA ----
        float* s_red = (float*)smbuf;                       // 8 KB
        int* s_i0 = (int*)(smbuf + 8192);
        int* s_i1 = s_i0 + 128; int* s_i2 = s_i1 + 128;
        int warp = tid >> 5, lane = tid & 31;
        int row0 = blockIdx.x * 128;
        if (tid < 128) {
            s_i0[tid] = pelem[row0 + tid];
            s_i1[tid] = paa[row0 + tid];
            s_i2[tid] = pbb[row0 + tid];
        }
        int batch = pbatch[row0];
        // E_bb rows held in registers (2 rows only)
        const ulonglong2* Pbg = (const ulonglong2*)g_Pbb;
        ulonglong2 b0a = Pbg[lane],      b0b = Pbg[32 + lane];
        ulonglong2 b1a = Pbg[64 + lane], b1b = Pbg[96 + lane];
        __syncthreads();
        u64 C0 = f2_pack(0.5f, 0.5f), C1 = f2_pack(0.25f, 0.25f),
            C2 = f2_pack(-1.f/48.f, -1.f/48.f);
        u64 acc00 = 0, acc01 = 0, acc10 = 0, acc11 = 0;
        const ulonglong2* Pe = (const ulonglong2*)g_Pelem;
        const ulonglong2* Pa = (const ulonglong2*)g_Paa;
        #pragma unroll 4
        for (int i = 0; i < 16; i++) {
            int r = warp * 16 + i;
            int e = s_i0[r] << 6, a = s_i1[r] << 6;
            bool ib = s_i2[r] != 0;
            ulonglong2 A0 = Pe[e + lane],      Bv0 = Pa[a + lane];
            ulonglong2 A1 = Pe[e + 32 + lane], Bv1 = Pa[a + 32 + lane];
            u64 c0x = ib ? b1a.x : b0a.x, c0y = ib ? b1a.y : b0a.y;
            u64 c1x = ib ? b1b.x : b0b.x, c1y = ib ? b1b.y : b0b.y;
            acc00 = silu_acc(acc00, A0.x, Bv0.x, c0x, C0, C1, C2);
            acc01 = silu_acc(acc01, A0.y, Bv0.y, c0y, C0, C1, C2);
            acc10 = silu_acc(acc10, A1.x, Bv1.x, c1x, C0, C1, C2);
            acc11 = silu_acc(acc11, A1.y, Bv1.y, c1y, C0, C1, C2);
        }
        float* my = s_red + warp * H_;
        ((ulonglong2*)my)[lane]         = make_ulonglong2(acc00, acc01);
        ((ulonglong2*)(my + 128))[lane] = make_ulonglong2(acc10, acc11);
        __syncthreads();
        float sum = 0.f;
        #pragma unroll
        for (int w = 0; w < 8; w++) sum += s_red[w * H_ + tid];
        atomicAdd(&g_pool[batch * H_ + tid], sum);
    } else if (blockIdx.x < 1152) {        // ---- ligand: histogram over 16 types ----
        int* s_cnt = (int*)smbuf;
        int bl = blockIdx.x - 1024;
        if (tid < 16) s_cnt[tid] = 0;
        __syncthreads();
        if (tid < 128) atomicAdd(&s_cnt[ltype[bl * 128 + tid]], 1);
        int batch = lbatch[bl * 128];
        __syncthreads();
        float sum = 0.f;
        #pragma unroll
        for (int t = 0; t < 16; t++) sum += (float)s_cnt[t] * g_sPlig[t * H_ + tid];
        g_pool[(B_ + batch) * H_ + tid] = sum;   // sole writer
    } else {                               // ---- distances ----
        float* s_x = (float*)smbuf;              // 4 KB each
        float* s_y = s_x + PP_;
        float* s_z = s_y + PP_;
        float* s_half = s_z + PP_;               // 1 KB
        float* s_d = s_half + 256;               // 0.5 KB
        int b = blockIdx.x - 1152;
        const float* pp = ppos + (size_t)b * PP_ * 3;
        for (int i = tid; i < PP_; i += 256) {
            s_x[i] = pp[3 * i]; s_y[i] = pp[3 * i + 1]; s_z[i] = pp[3 * i + 2];
        }
        __syncthreads();
        int lig = tid & (LP_ - 1), half = tid >> 7;       // half: 512 pts each
        const float* lp = lpos + ((size_t)b * LP_ + lig) * 3;
        float lx = lp[0], ly = lp[1], lz = lp[2];
        u64 NX = f2_pack(-lx, -lx), NY = f2_pack(-ly, -ly), NZ = f2_pack(-lz, -lz);
        const ulonglong2* sx = (const ulonglong2*)s_x + half * 128;
        const ulonglong2* sy = (const ulonglong2*)s_y + half * 128;
        const ulonglong2* sz = (const ulonglong2*)s_z + half * 128;
        float m0 = 3.4e38f, m1 = 3.4e38f, m2 = 3.4e38f, m3 = 3.4e38f;
        #pragma unroll 4
        for (int i = 0; i < 128; i++) {
            ulonglong2 X = sx[i], Y = sy[i], Z = sz[i];
            u64 dx = f2_add(X.x, NX), dy = f2_add(Y.x, NY), dz = f2_add(Z.x, NZ);
            u64 d2 = f2_fma(dz, dz, f2_fma(dy, dy, f2_mul(dx, dx)));
            float2 u = f2_unpack(d2);
            m0 = fminf(m0, u.x); m1 = fminf(m1, u.y);
            dx = f2_add(X.y, NX); dy = f2_add(Y.y, NY); dz = f2_add(Z.y, NZ);
            d2 = f2_fma(dz, dz, f2_fma(dy, dy, f2_mul(dx, dx)));
            u = f2_unpack(d2);
            m2 = fminf(m2, u.x); m3 = fminf(m3, u.y);
        }
        s_half[tid] = fminf(fminf(m0, m1), fminf(m2, m3));
        __syncthreads();
        if (tid < 128) s_d[tid] = sqrtf(fminf(s_half[tid], s_half[tid + 128]));
        __syncthreads();
        if (tid < 32) {
            float sum = 0.f, mn = 3.4e38f;
            #pragma unroll
            for (int i = 0; i < 4; i++) { float v = s_d[tid + 32 * i]; sum += v; mn = fminf(mn, v); }
            #pragma unroll
            for (int o = 16; o > 0; o >>= 1) {
                sum += __shfl_xor_sync(0xffffffffu, sum, o);
                mn = fminf(mn, __shfl_xor_sync(0xffffffffu, mn, o));
            }
            if (tid == 0) { g_contact[2 * b] = sum * (1.f / LP_); g_contact[2 * b + 1] = mn; }
        }
    }
}

// ================= K3: pre-activation GEMM partials (parallel, smem-staged) =================
// grid 256: kt = bid>>5 (8 k-chunks of 64), rr = bid&31: ct = rr&1 (col half), bg = rr>>1 (16 batch groups of 8)
__global__ __launch_bounds__(256) void k_aff1()
{
    __shared__ float s_at[64 * 8];      // means transposed: [kl*8 + bb]   (2 KB)
    __shared__ float s_m[64 * 128];     // M chunk                          (32 KB)
    int bid = blockIdx.x, tid = threadIdx.x;
    int kt = bid >> 5, rr = bid & 31, ct = rr & 1, bg = rr >> 1;
    for (int idx = tid; idx < 512; idx += 256) {
        int kl = idx >> 3, bb = idx & 7;
        int k = kt * 64 + kl, b = bg * 8 + bb;
        s_at[idx] = (k < 256) ? g_pool[b * H_ + k] * (1.f / PP_)
                              : g_pool[(B_ + b) * H_ + (k - 256)] * (1.f / LP_);
    }
    const float4* gm4 = (const float4*)g_M;
    float4* sm4 = (float4*)s_m;
    #pragma unroll
    for (int idx = tid; idx < 2048; idx += 256) {     // 8 independent float4 loads/thread
        int kl = idx >> 5, jc = idx & 31;
        sm4[kl * 32 + jc] = gm4[(kt * 64 + kl) * 64 + ct * 32 + jc];
    }
    __syncthreads();
    int j = tid & 127, p = tid >> 7;
    float a0 = 0, a1 = 0, a2 = 0, a3 = 0;
    const float4* sa4 = (const float4*)s_at;          // index kl*2 + p
    #pragma unroll 8
    for (int kl = 0; kl < 64; kl++) {
        float w = s_m[kl * 128 + j];
        float4 av = sa4[kl * 2 + p];
        a0 += av.x * w; a1 += av.y * w; a2 += av.z * w; a3 += av.w * w;
    }
    int jj = ct * 128 + j, b0 = bg * 8 + p * 4;
    atomicAdd(&g_act[(b0 + 0) * H_ + jj], a0);
    atomicAdd(&g_act[(b0 + 1) * H_ + jj], a1);
    atomicAdd(&g_act[(b0 + 2) * H_ + jj], a2);
    atomicAdd(&g_act[(b0 + 3) * H_ + jj], a3);
}

// ================= K4: contact + bias + exact silu + output dot =================
__global__ __launch_bounds__(256) void k_aff2(
    const float* __restrict__ Wa1, const float* __restrict__ Wa2,
    const float* __restrict__ ba2, float* __restrict__ out)
{
    __shared__ float s_w[8];
    int b = blockIdx.x, j = threadIdx.x;
    float a = g_act[b * H_ + j] + g_bvec[j]
            + g_contact[2 * b]     * Wa1[512 * H_ + j]
            + g_contact[2 * b + 1] * Wa1[513 * H_ + j];
    float h = a / (1.f + expf(-a));
    float v = h * Wa2[j];
    #pragma unroll
    for (int o = 16; o > 0; o >>= 1) v += __shfl_xor_sync(0xffffffffu, v, o);
    int warp = j >> 5, lane = j & 31;
    if (lane == 0) s_w[warp] = v;
    __syncthreads();
    if (j == 0) {
        float t = 0.f;
        #pragma unroll
        for (int w = 0; w < 8; w++) t += s_w[w];
        out[b] = t + ba2[0];
    }
}

extern "C" void kernel_launch(void* const* d_in, const int* in_sizes, int n_in,
                              void* d_out, int out_size) {
    const float* protein_pos     = (const float*)d_in[0];
    const float* ligand_pos      = (const float*)d_in[1];
    const int*   protein_element = (const int*)  d_in[2];
    const int*   protein_aa      = (const int*)  d_in[3];
    const int*   protein_bb      = (const int*)  d_in[4];
    const int*   ligand_type     = (const int*)  d_in[5];
    const int*   protein_batch   = (const int*)  d_in[6];
    const int*   ligand_batch    = (const int*)  d_in[7];
    const float* E_elem          = (const float*)d_in[8];
    const float* E_aa            = (const float*)d_in[9];
    const float* E_bb            = (const float*)d_in[10];
    const float* E_lig           = (const float*)d_in[11];
    const float* Wd1             = (const float*)d_in[12];
    const float* bd1             = (const float*)d_in[13];
    const float* Wd2             = (const float*)d_in[14];
    const float* bd2             = (const float*)d_in[15];
    const float* Wa1             = (const float*)d_in[16];
    const float* ba1             = (const float*)d_in[17];
    const float* Wa2             = (const float*)d_in[18];
    const float* ba2             = (const float*)d_in[19];
    float* out = (float*)d_out;

    k_stage1<<<190, 256>>>(E_elem, E_aa, E_bb, E_lig, Wd1, bd1, Wd2,
                           Wa1, ba1, bd2);
    k_fused <<<1280, 256>>>(protein_element, protein_aa, protein_bb,
                            protein_batch, ligand_type, ligand_batch,
                            protein_pos, ligand_pos);
    k_aff1  <<<256, 256>>>();
    k_aff2  <<<B_, 256>>>(Wa1, Wa2, ba2, out);
}